// round 5
// baseline (speedup 1.0000x reference)
#include <cuda_runtime.h>
#include <math.h>

#define HD 256      // hidden dim
#define BB 2        // batch
#define LL 512      // seq len (L1 == L2)
#define NHEAD 8
#define DHEAD 32

// ---------------- scratch (device globals; no allocation) ----------------
__device__ float g_q [BB*LL*HD];                 // 1 MB
__device__ float g_k [BB*LL*HD];                 // 1 MB
__device__ float g_h1[BB*LL*HD];                 // 1 MB (includes +b1)
__device__ float g_h2[BB*LL*HD];                 // 1 MB
__device__ float g_logits[(size_t)BB*NHEAD*LL*LL]; // 16 MB

// ---------------- packed fp32x2 helpers (Blackwell) ----------------
typedef unsigned long long u64p;

__device__ __forceinline__ u64p f2_pack(float lo, float hi) {
    u64p r; asm("mov.b64 %0, {%1, %2};" : "=l"(r) : "f"(lo), "f"(hi)); return r;
}
__device__ __forceinline__ void f2_unpack(u64p p, float& lo, float& hi) {
    asm("mov.b64 {%0, %1}, %2;" : "=f"(lo), "=f"(hi) : "l"(p));
}
__device__ __forceinline__ u64p f2_fma(u64p a, u64p b, u64p c) {
    u64p d; asm("fma.rn.f32x2 %0, %1, %2, %3;" : "=l"(d) : "l"(a), "l"(b), "l"(c)); return d;
}
__device__ __forceinline__ u64p f2_add(u64p a, u64p b) {
    u64p d; asm("add.rn.f32x2 %0, %1, %2;" : "=l"(d) : "l"(a), "l"(b)); return d;
}
__device__ __forceinline__ u64p f2_relu(u64p x) {
    float lo, hi; f2_unpack(x, lo, hi);
    lo = fmaxf(lo, 0.0f); hi = fmaxf(hi, 0.0f);
    return f2_pack(lo, hi);
}

// =========================================================================
// K1: projections.  job z: 0=q 1=k 2=h1(+b1) 3=h2
// C[m,o] = sum_c A[m,c]*W[o*ldw + c] (+ bias[o]);  M=1024, N=256 per job
// Tile 64(i) x 32(j), 256 threads, grid (8,16,4)=512 blocks.
// acc packed along i; W stored DUPLICATED in smem -> no pack MOVs.
// =========================================================================
__global__ __launch_bounds__(256) void proj_kernel(
    const float* __restrict__ e1, const float* __restrict__ e2,
    const float* __restrict__ ipw, const float* __restrict__ ipb,
    const float* __restrict__ W1,  const float* __restrict__ b1)
{
    const int job = blockIdx.z;
    const float* A; const float* W; const float* bias; int ldw; float* C;
    if (job == 0)      { A = e1; W = ipw;           bias = ipb;      ldw = HD;   C = g_q;  }
    else if (job == 1) { A = e2; W = ipw + HD*HD;   bias = ipb + HD; ldw = HD;   C = g_k;  }
    else if (job == 2) { A = e1; W = W1;            bias = b1;       ldw = 2*HD; C = g_h1; }
    else               { A = e2; W = W1 + HD;       bias = nullptr;  ldw = 2*HD; C = g_h2; }

    const int i0 = blockIdx.y * 64;
    const int j0 = blockIdx.x * 32;

    __shared__ __align__(16) float sA [32][68];   // [kk][i] 64 used
    __shared__ __align__(16) float sWd[32][68];   // [kk][2j] duplicated pairs

    const int tid = threadIdx.x;
    const int ty = tid >> 4;       // 0..15 -> 4 rows
    const int tx = tid & 15;       // 0..15 -> 2 cols

    const int lm  = tid >> 3;        // 0..31
    const int lk4 = (tid & 7) * 4;   // 0..28

    u64p acc[2][2] = {};   // [i-pair][j]

    for (int k0 = 0; k0 < HD; k0 += 32) {
        float4 va0 = *(const float4*)&A[(size_t)(i0 + lm)      * HD  + k0 + lk4];
        float4 va1 = *(const float4*)&A[(size_t)(i0 + 32 + lm) * HD  + k0 + lk4];
        float4 vw  = *(const float4*)&W[(size_t)(j0 + lm)      * ldw + k0 + lk4];
        __syncthreads();
        sA[lk4+0][lm] = va0.x; sA[lk4+1][lm] = va0.y; sA[lk4+2][lm] = va0.z; sA[lk4+3][lm] = va0.w;
        sA[lk4+0][32+lm] = va1.x; sA[lk4+1][32+lm] = va1.y; sA[lk4+2][32+lm] = va1.z; sA[lk4+3][32+lm] = va1.w;
        *(float2*)&sWd[lk4+0][2*lm] = make_float2(vw.x, vw.x);
        *(float2*)&sWd[lk4+1][2*lm] = make_float2(vw.y, vw.y);
        *(float2*)&sWd[lk4+2][2*lm] = make_float2(vw.z, vw.z);
        *(float2*)&sWd[lk4+3][2*lm] = make_float2(vw.w, vw.w);
        __syncthreads();

#pragma unroll
        for (int kk = 0; kk < 32; kk++) {
            const ulonglong2 ap = *(const ulonglong2*)&sA [kk][ty*4];  // 2 i-pairs
            const ulonglong2 wd = *(const ulonglong2*)&sWd[kk][tx*4];  // (wx,wx),(wy,wy)
            acc[0][0] = f2_fma(ap.x, wd.x, acc[0][0]);
            acc[0][1] = f2_fma(ap.x, wd.y, acc[0][1]);
            acc[1][0] = f2_fma(ap.y, wd.x, acc[1][0]);
            acc[1][1] = f2_fma(ap.y, wd.y, acc[1][1]);
        }
    }

    float bv0 = 0.f, bv1 = 0.f;
    if (bias) { bv0 = bias[j0 + tx*2]; bv1 = bias[j0 + tx*2 + 1]; }
#pragma unroll
    for (int p = 0; p < 2; p++) {
        float c0lo, c0hi, c1lo, c1hi;
        f2_unpack(acc[p][0], c0lo, c0hi);  // rows 4ty+2p, 4ty+2p+1 @ col 2tx
        f2_unpack(acc[p][1], c1lo, c1hi);  //                        @ col 2tx+1
        const int r = i0 + ty*4 + 2*p;
        *(float2*)&C[(size_t)(r+0) * HD + j0 + tx*2] = make_float2(c0lo + bv0, c1lo + bv1);
        *(float2*)&C[(size_t)(r+1) * HD + j0 + tx*2] = make_float2(c0hi + bv0, c1hi + bv1);
    }
}

// =========================================================================
// K2: logits[b,h,i,j] = (1/sqrt(32)) * sum_d q[..]*k[..]
// grid (8,8,16)=1024 blocks; tile 64x64, K=32, 4i x 4j per thread.
// =========================================================================
__global__ __launch_bounds__(256) void logits_kernel()
{
    const int bh = blockIdx.z;
    const int b  = bh >> 3, h = bh & 7;
    const float* Q  = g_q + (size_t)b * LL * HD + h * DHEAD;
    const float* Kp = g_k + (size_t)b * LL * HD + h * DHEAD;
    float* C = g_logits + (size_t)bh * LL * LL;

    const int i0 = blockIdx.y * 64;
    const int j0 = blockIdx.x * 64;

    __shared__ __align__(16) float sA [32][68];    // [kk][i] 64
    __shared__ __align__(16) float sKd[32][132];   // [kk][2j] 128 duplicated

    const int tid = threadIdx.x;
    const int ty = tid >> 4;       // rows 4ty..+3
    const int tx = tid & 15;       // cols 4tx..+3

    const int lm  = tid >> 3;        // 0..31
    const int lk4 = (tid & 7) * 4;   // 0..28

    {
        float4 va0 = *(const float4*)&Q [(size_t)(i0 + lm)      * HD + lk4];
        float4 va1 = *(const float4*)&Q [(size_t)(i0 + 32 + lm) * HD + lk4];
        float4 vk0 = *(const float4*)&Kp[(size_t)(j0 + lm)      * HD + lk4];
        float4 vk1 = *(const float4*)&Kp[(size_t)(j0 + 32 + lm) * HD + lk4];
        sA[lk4+0][lm] = va0.x; sA[lk4+1][lm] = va0.y; sA[lk4+2][lm] = va0.z; sA[lk4+3][lm] = va0.w;
        sA[lk4+0][32+lm] = va1.x; sA[lk4+1][32+lm] = va1.y; sA[lk4+2][32+lm] = va1.z; sA[lk4+3][32+lm] = va1.w;
        *(float2*)&sKd[lk4+0][2*lm] = make_float2(vk0.x, vk0.x);
        *(float2*)&sKd[lk4+1][2*lm] = make_float2(vk0.y, vk0.y);
        *(float2*)&sKd[lk4+2][2*lm] = make_float2(vk0.z, vk0.z);
        *(float2*)&sKd[lk4+3][2*lm] = make_float2(vk0.w, vk0.w);
        *(float2*)&sKd[lk4+0][64+2*lm] = make_float2(vk1.x, vk1.x);
        *(float2*)&sKd[lk4+1][64+2*lm] = make_float2(vk1.y, vk1.y);
        *(float2*)&sKd[lk4+2][64+2*lm] = make_float2(vk1.z, vk1.z);
        *(float2*)&sKd[lk4+3][64+2*lm] = make_float2(vk1.w, vk1.w);
    }
    __syncthreads();

    u64p acc[2][4] = {};   // [i-pair][j]
#pragma unroll
    for (int kk = 0; kk < 32; kk++) {
        const ulonglong2 ap  = *(const ulonglong2*)&sA [kk][ty*4];
        const ulonglong2 kd0 = *(const ulonglong2*)&sKd[kk][tx*8];
        const ulonglong2 kd1 = *(const ulonglong2*)&sKd[kk][tx*8 + 4];
        acc[0][0] = f2_fma(ap.x, kd0.x, acc[0][0]);
        acc[0][1] = f2_fma(ap.x, kd0.y, acc[0][1]);
        acc[0][2] = f2_fma(ap.x, kd1.x, acc[0][2]);
        acc[0][3] = f2_fma(ap.x, kd1.y, acc[0][3]);
        acc[1][0] = f2_fma(ap.y, kd0.x, acc[1][0]);
        acc[1][1] = f2_fma(ap.y, kd0.y, acc[1][1]);
        acc[1][2] = f2_fma(ap.y, kd1.x, acc[1][2]);
        acc[1][3] = f2_fma(ap.y, kd1.y, acc[1][3]);
    }

    const float scale = 0.1767766952966369f; // 1/sqrt(32)
#pragma unroll
    for (int p = 0; p < 2; p++) {
        float lo[4], hi[4];
#pragma unroll
        for (int c = 0; c < 4; c++) f2_unpack(acc[p][c], lo[c], hi[c]);
        const int r = i0 + ty*4 + 2*p;
        *(float4*)&C[(size_t)(r+0) * LL + j0 + tx*4] =
            make_float4(lo[0]*scale, lo[1]*scale, lo[2]*scale, lo[3]*scale);
        *(float4*)&C[(size_t)(r+1) * LL + j0 + tx*4] =
            make_float4(hi[0]*scale, hi[1]*scale, hi[2]*scale, hi[3]*scale);
    }
}

// =========================================================================
// K3: softmax + head-mean.  One block per (b,i); warp h owns head h's row.
// =========================================================================
__global__ __launch_bounds__(256) void softmax_mean_kernel(float* __restrict__ out)
{
    const int b = blockIdx.x >> 9;
    const int i = blockIdx.x & 511;
    const int wid  = threadIdx.x >> 5;
    const int lane = threadIdx.x & 31;

    __shared__ float p[8][512];

    const float* row = g_logits + ((size_t)(b*8 + wid) * LL + i) * LL;

    float v[16];
    float mx = -1e30f;
#pragma unroll
    for (int r = 0; r < 16; r++) {
        v[r] = row[lane + 32*r];
        mx = fmaxf(mx, v[r]);
    }
#pragma unroll
    for (int o = 16; o; o >>= 1) mx = fmaxf(mx, __shfl_xor_sync(0xffffffffu, mx, o));

    float s = 0.0f;
#pragma unroll
    for (int r = 0; r < 16; r++) { v[r] = __expf(v[r] - mx); s += v[r]; }
#pragma unroll
    for (int o = 16; o; o >>= 1) s += __shfl_xor_sync(0xffffffffu, s, o);
    const float inv = 1.0f / s;

#pragma unroll
    for (int r = 0; r < 16; r++) p[wid][lane + 32*r] = v[r] * inv;

    __syncthreads();

    const int t = threadIdx.x;
    const size_t o = ((size_t)b * LL + i) * LL;
#pragma unroll
    for (int jj = 0; jj < 2; jj++) {
        int j = t + jj * 256;
        float a = 0.0f;
#pragma unroll
        for (int h = 0; h < 8; h++) a += p[h][j];
        out[o + j] = a * 0.125f;
    }
}

// =========================================================================
// K4: match_scores[b,i,j] = sigmoid( sum_c relu(h1[b,i,c]+h2[b,j,c]) * w2[c] + b2 )
// Tile 32x32, 256 threads, 2i x 2j per thread -> grid (16,16,2)=512 blocks.
// B and w2 duplicated in smem; packed FADD2/FFMA2; scalar FMNMX relu.
// =========================================================================
__global__ __launch_bounds__(256) void match_kernel(
    const float* __restrict__ W2, const float* __restrict__ b2,
    float* __restrict__ out)
{
    const int b  = blockIdx.z;
    const int i0 = blockIdx.y * 32;
    const int j0 = blockIdx.x * 32;

    const float* A  = g_h1 + (size_t)b * LL * HD;
    const float* Bm = g_h2 + (size_t)b * LL * HD;

    __shared__ __align__(16) float sA [32][34];   // [kk][i]  (even stride -> LDS.64 aligned)
    __shared__ __align__(16) float sBd[32][68];   // [kk][2j] duplicated
    __shared__ __align__(16) float2 sw2d[HD];     // (w,w) pairs

    const int tid = threadIdx.x;
    const int ty = tid >> 4;       // rows 2ty, 2ty+1
    const int tx = tid & 15;       // cols 2tx, 2tx+1

    sw2d[tid] = make_float2(W2[tid], W2[tid]);   // tid < 256 == HD
    const u64p* swd = (const u64p*)sw2d;

    const int lm  = tid >> 3;        // 0..31
    const int lk4 = (tid & 7) * 4;   // 0..28

    u64p acc0 = 0, acc1 = 0;  // cols 2tx, 2tx+1; each packed over rows (2ty, 2ty+1)

    for (int k0 = 0; k0 < HD; k0 += 32) {
        float4 va = *(const float4*)&A [(size_t)(i0 + lm) * HD + k0 + lk4];
        float4 vb = *(const float4*)&Bm[(size_t)(j0 + lm) * HD + k0 + lk4];
        __syncthreads();
        sA[lk4+0][lm] = va.x; sA[lk4+1][lm] = va.y; sA[lk4+2][lm] = va.z; sA[lk4+3][lm] = va.w;
        *(float2*)&sBd[lk4+0][2*lm] = make_float2(vb.x, vb.x);
        *(float2*)&sBd[lk4+1][2*lm] = make_float2(vb.y, vb.y);
        *(float2*)&sBd[lk4+2][2*lm] = make_float2(vb.z, vb.z);
        *(float2*)&sBd[lk4+3][2*lm] = make_float2(vb.w, vb.w);
        __syncthreads();

#pragma unroll
        for (int kk = 0; kk < 32; kk++) {
            const u64p       ap = *(const u64p*)&sA[kk][ty*2];        // (A_i, A_i+1)
            const ulonglong2 bp = *(const ulonglong2*)&sBd[kk][tx*4]; // (bx,bx),(by,by)
            const u64p       wd = swd[k0 + kk];                       // (w,w)
            acc0 = f2_fma(f2_relu(f2_add(ap, bp.x)), wd, acc0);
            acc1 = f2_fma(f2_relu(f2_add(ap, bp.y)), wd, acc1);
        }
    }

    const float bias2 = b2[0];
    const size_t base = (size_t)BB * LL * LL + (size_t)b * LL * LL;

    float s00, s10, s01, s11;
    f2_unpack(acc0, s00, s10);   // col 2tx  : rows 2ty, 2ty+1
    f2_unpack(acc1, s01, s11);   // col 2tx+1: rows 2ty, 2ty+1

    const int col = j0 + tx*2;
    const int r0  = i0 + ty*2;
    float2 o0 = make_float2(1.0f/(1.0f+__expf(-(s00+bias2))), 1.0f/(1.0f+__expf(-(s01+bias2))));
    float2 o1 = make_float2(1.0f/(1.0f+__expf(-(s10+bias2))), 1.0f/(1.0f+__expf(-(s11+bias2))));
    *(float2*)&out[base + (size_t)(r0+0) * LL + col] = o0;
    *(float2*)&out[base + (size_t)(r0+1) * LL + col] = o1;
}

// =========================================================================
extern "C" void kernel_launch(void* const* d_in, const int* in_sizes, int n_in,
                              void* d_out, int out_size)
{
    const float* e1  = (const float*)d_in[0];  // (B,L1,H)
    const float* e2  = (const float*)d_in[1];  // (B,L2,H)
    const float* ipw = (const float*)d_in[2];  // (3H,H)
    const float* ipb = (const float*)d_in[3];  // (3H,)
    const float* W1  = (const float*)d_in[4];  // (H,2H)
    const float* b1  = (const float*)d_in[5];  // (H,)
    const float* W2  = (const float*)d_in[6];  // (1,H)
    const float* b2  = (const float*)d_in[7];  // (1,)
    float* out = (float*)d_out;                // [attn (B,L1,L2)] ++ [match (B,L1,L2)]

    proj_kernel   <<<dim3(HD/32, (BB*LL)/64, 4), 256>>>(e1, e2, ipw, ipb, W1, b1);
    logits_kernel <<<dim3(LL/64, LL/64, BB*NHEAD), 256>>>();
    softmax_mean_kernel<<<BB*LL, 256>>>(out);
    match_kernel  <<<dim3(LL/32, LL/32, BB), 256>>>(W2, b2, out);
}

// round 6
// speedup vs baseline: 1.1455x; 1.1455x over previous
#include <cuda_runtime.h>
#include <math.h>

#define HD 256      // hidden dim
#define BB 2        // batch
#define LL 512      // seq len (L1 == L2)
#define NHEAD 8
#define DHEAD 32

// ---------------- scratch (device globals; no allocation) ----------------
__device__ float g_q [BB*LL*HD];                 // 1 MB
__device__ float g_k [BB*LL*HD];                 // 1 MB
__device__ float g_h1[BB*LL*HD];                 // 1 MB (includes +b1)
__device__ float g_h2[BB*LL*HD];                 // 1 MB
__device__ float g_logits[(size_t)BB*NHEAD*LL*LL]; // 16 MB; reused for match partials

// ---------------- packed fp32x2 helpers (Blackwell) ----------------
typedef unsigned long long u64p;

__device__ __forceinline__ void f2_unpack(u64p p, float& lo, float& hi) {
    asm("mov.b64 {%0, %1}, %2;" : "=f"(lo), "=f"(hi) : "l"(p));
}
__device__ __forceinline__ u64p f2_fma(u64p a, u64p b, u64p c) {
    u64p d; asm("fma.rn.f32x2 %0, %1, %2, %3;" : "=l"(d) : "l"(a), "l"(b), "l"(c)); return d;
}
__device__ __forceinline__ u64p f2_add(u64p a, u64p b) {
    u64p d; asm("add.rn.f32x2 %0, %1, %2;" : "=l"(d) : "l"(a), "l"(b)); return d;
}
__device__ __forceinline__ u64p f2_relu(u64p x) {
    float lo, hi; f2_unpack(x, lo, hi);
    lo = fmaxf(lo, 0.0f); hi = fmaxf(hi, 0.0f);
    u64p r; asm("mov.b64 %0, {%1, %2};" : "=l"(r) : "f"(lo), "f"(hi)); return r;
}

// =========================================================================
// K1: projections.  job z: 0=q 1=k 2=h1(+b1) 3=h2
// Tile 64(i) x 32(j), 256 threads, grid (8,16,4)=512 blocks, 4i x 2j/thread.
// A duplicated in smem (broadcast side), W plain -> true j-pairs, no MOVs.
// =========================================================================
__global__ __launch_bounds__(256) void proj_kernel(
    const float* __restrict__ e1, const float* __restrict__ e2,
    const float* __restrict__ ipw, const float* __restrict__ ipb,
    const float* __restrict__ W1,  const float* __restrict__ b1)
{
    const int job = blockIdx.z;
    const float* A; const float* W; const float* bias; int ldw; float* C;
    if (job == 0)      { A = e1; W = ipw;           bias = ipb;      ldw = HD;   C = g_q;  }
    else if (job == 1) { A = e2; W = ipw + HD*HD;   bias = ipb + HD; ldw = HD;   C = g_k;  }
    else if (job == 2) { A = e1; W = W1;            bias = b1;       ldw = 2*HD; C = g_h1; }
    else               { A = e2; W = W1 + HD;       bias = nullptr;  ldw = 2*HD; C = g_h2; }

    const int i0 = blockIdx.y * 64;
    const int j0 = blockIdx.x * 32;

    __shared__ __align__(16) float sAd[32][132];  // [kk][2i] duplicated, 128 used
    __shared__ __align__(16) float sW [32][36];   // [kk][j]  plain, 32 used

    const int tid = threadIdx.x;
    const int ty = tid >> 4;       // rows 4ty..4ty+3
    const int tx = tid & 15;       // cols 2tx, 2tx+1

    const int lm  = tid >> 3;        // 0..31
    const int lk4 = (tid & 7) * 4;   // 0..28

    u64p acc[4] = {};   // row u -> (col 2tx, col 2tx+1)

    for (int k0 = 0; k0 < HD; k0 += 32) {
        float4 va0 = *(const float4*)&A[(size_t)(i0 + lm)      * HD  + k0 + lk4];
        float4 va1 = *(const float4*)&A[(size_t)(i0 + 32 + lm) * HD  + k0 + lk4];
        float4 vw  = *(const float4*)&W[(size_t)(j0 + lm)      * ldw + k0 + lk4];
        __syncthreads();
        *(float2*)&sAd[lk4+0][2*lm]      = make_float2(va0.x, va0.x);
        *(float2*)&sAd[lk4+1][2*lm]      = make_float2(va0.y, va0.y);
        *(float2*)&sAd[lk4+2][2*lm]      = make_float2(va0.z, va0.z);
        *(float2*)&sAd[lk4+3][2*lm]      = make_float2(va0.w, va0.w);
        *(float2*)&sAd[lk4+0][64+2*lm]   = make_float2(va1.x, va1.x);
        *(float2*)&sAd[lk4+1][64+2*lm]   = make_float2(va1.y, va1.y);
        *(float2*)&sAd[lk4+2][64+2*lm]   = make_float2(va1.z, va1.z);
        *(float2*)&sAd[lk4+3][64+2*lm]   = make_float2(va1.w, va1.w);
        sW[lk4+0][lm] = vw.x; sW[lk4+1][lm] = vw.y; sW[lk4+2][lm] = vw.z; sW[lk4+3][lm] = vw.w;
        __syncthreads();

#pragma unroll
        for (int kk = 0; kk < 32; kk++) {
            const ulonglong2 ad0 = *(const ulonglong2*)&sAd[kk][ty*8];     // (a0,a0),(a1,a1)
            const ulonglong2 ad1 = *(const ulonglong2*)&sAd[kk][ty*8 + 4]; // (a2,a2),(a3,a3)
            const u64p       wp  = *(const u64p*)&sW[kk][tx*2];            // (w0,w1)
            acc[0] = f2_fma(ad0.x, wp, acc[0]);
            acc[1] = f2_fma(ad0.y, wp, acc[1]);
            acc[2] = f2_fma(ad1.x, wp, acc[2]);
            acc[3] = f2_fma(ad1.y, wp, acc[3]);
        }
    }

    float bv0 = 0.f, bv1 = 0.f;
    if (bias) { bv0 = bias[j0 + tx*2]; bv1 = bias[j0 + tx*2 + 1]; }
#pragma unroll
    for (int u = 0; u < 4; u++) {
        float c0, c1;
        f2_unpack(acc[u], c0, c1);
        *(float2*)&C[(size_t)(i0 + ty*4 + u) * HD + j0 + tx*2] = make_float2(c0 + bv0, c1 + bv1);
    }
}

// =========================================================================
// K2: logits[b,h,i,j] = (1/sqrt(32)) * sum_d q*k
// grid (8,8,16)=1024; tile 64x64, K=32, 4i x 4j/thread.
// Q duplicated, K plain -> true j-pairs.
// =========================================================================
__global__ __launch_bounds__(256) void logits_kernel()
{
    const int bh = blockIdx.z;
    const int b  = bh >> 3, h = bh & 7;
    const float* Q  = g_q + (size_t)b * LL * HD + h * DHEAD;
    const float* Kp = g_k + (size_t)b * LL * HD + h * DHEAD;
    float* C = g_logits + (size_t)bh * LL * LL;

    const int i0 = blockIdx.y * 64;
    const int j0 = blockIdx.x * 64;

    __shared__ __align__(16) float sQd[32][132];  // [kk][2i] duplicated
    __shared__ __align__(16) float sK [32][68];   // [kk][j] plain, 64 used

    const int tid = threadIdx.x;
    const int ty = tid >> 4;       // rows 4ty..+3
    const int tx = tid & 15;       // cols 4tx..+3 (2 pairs)

    const int lm  = tid >> 3;        // 0..31
    const int lk4 = (tid & 7) * 4;   // 0..28

    {
        float4 vq0 = *(const float4*)&Q [(size_t)(i0 + lm)      * HD + lk4];
        float4 vq1 = *(const float4*)&Q [(size_t)(i0 + 32 + lm) * HD + lk4];
        float4 vk0 = *(const float4*)&Kp[(size_t)(j0 + lm)      * HD + lk4];
        float4 vk1 = *(const float4*)&Kp[(size_t)(j0 + 32 + lm) * HD + lk4];
        *(float2*)&sQd[lk4+0][2*lm]    = make_float2(vq0.x, vq0.x);
        *(float2*)&sQd[lk4+1][2*lm]    = make_float2(vq0.y, vq0.y);
        *(float2*)&sQd[lk4+2][2*lm]    = make_float2(vq0.z, vq0.z);
        *(float2*)&sQd[lk4+3][2*lm]    = make_float2(vq0.w, vq0.w);
        *(float2*)&sQd[lk4+0][64+2*lm] = make_float2(vq1.x, vq1.x);
        *(float2*)&sQd[lk4+1][64+2*lm] = make_float2(vq1.y, vq1.y);
        *(float2*)&sQd[lk4+2][64+2*lm] = make_float2(vq1.z, vq1.z);
        *(float2*)&sQd[lk4+3][64+2*lm] = make_float2(vq1.w, vq1.w);
        sK[lk4+0][lm]    = vk0.x; sK[lk4+1][lm]    = vk0.y; sK[lk4+2][lm]    = vk0.z; sK[lk4+3][lm]    = vk0.w;
        sK[lk4+0][32+lm] = vk1.x; sK[lk4+1][32+lm] = vk1.y; sK[lk4+2][32+lm] = vk1.z; sK[lk4+3][32+lm] = vk1.w;
    }
    __syncthreads();

    u64p acc[4][2] = {};   // [row u][j-pair p]
#pragma unroll
    for (int kk = 0; kk < 32; kk++) {
        const ulonglong2 qd0 = *(const ulonglong2*)&sQd[kk][ty*8];
        const ulonglong2 qd1 = *(const ulonglong2*)&sQd[kk][ty*8 + 4];
        const ulonglong2 kp  = *(const ulonglong2*)&sK [kk][tx*4];  // (k0,k1),(k2,k3)
        acc[0][0] = f2_fma(qd0.x, kp.x, acc[0][0]);
        acc[0][1] = f2_fma(qd0.x, kp.y, acc[0][1]);
        acc[1][0] = f2_fma(qd0.y, kp.x, acc[1][0]);
        acc[1][1] = f2_fma(qd0.y, kp.y, acc[1][1]);
        acc[2][0] = f2_fma(qd1.x, kp.x, acc[2][0]);
        acc[2][1] = f2_fma(qd1.x, kp.y, acc[2][1]);
        acc[3][0] = f2_fma(qd1.y, kp.x, acc[3][0]);
        acc[3][1] = f2_fma(qd1.y, kp.y, acc[3][1]);
    }

    const float scale = 0.1767766952966369f; // 1/sqrt(32)
#pragma unroll
    for (int u = 0; u < 4; u++) {
        float c0, c1, c2, c3;
        f2_unpack(acc[u][0], c0, c1);
        f2_unpack(acc[u][1], c2, c3);
        *(float4*)&C[(size_t)(i0 + ty*4 + u) * LL + j0 + tx*4] =
            make_float4(c0*scale, c1*scale, c2*scale, c3*scale);
    }
}

// =========================================================================
// K3: softmax + head-mean.  One block per (b,i); warp h owns head h's row.
// =========================================================================
__global__ __launch_bounds__(256) void softmax_mean_kernel(float* __restrict__ out)
{
    const int b = blockIdx.x >> 9;
    const int i = blockIdx.x & 511;
    const int wid  = threadIdx.x >> 5;
    const int lane = threadIdx.x & 31;

    __shared__ float p[8][512];

    const float* row = g_logits + ((size_t)(b*8 + wid) * LL + i) * LL;

    float v[16];
    float mx = -1e30f;
#pragma unroll
    for (int r = 0; r < 16; r++) {
        v[r] = row[lane + 32*r];
        mx = fmaxf(mx, v[r]);
    }
#pragma unroll
    for (int o = 16; o; o >>= 1) mx = fmaxf(mx, __shfl_xor_sync(0xffffffffu, mx, o));

    float s = 0.0f;
#pragma unroll
    for (int r = 0; r < 16; r++) { v[r] = __expf(v[r] - mx); s += v[r]; }
#pragma unroll
    for (int o = 16; o; o >>= 1) s += __shfl_xor_sync(0xffffffffu, s, o);
    const float inv = 1.0f / s;

#pragma unroll
    for (int r = 0; r < 16; r++) p[wid][lane + 32*r] = v[r] * inv;

    __syncthreads();

    const int t = threadIdx.x;
    const size_t o = ((size_t)b * LL + i) * LL;
#pragma unroll
    for (int jj = 0; jj < 2; jj++) {
        int j = t + jj * 256;
        float a = 0.0f;
#pragma unroll
        for (int h = 0; h < 8; h++) a += p[h][j];
        out[o + j] = a * 0.125f;
    }
}

// =========================================================================
// K4: match partial sums over a 128-channel split.
// P[((s*BB+b)*LL+i)*LL+j] = sum_{c in split s} relu(h1[i,c]+h2[j,c])*w2[c]
// Tile 64i x 32j, 256 threads, grid (16,8,4)=512 blocks (z = b*2+s).
// A duplicated (broadcast), B plain -> true j-pairs, w2 duplicated table.
// =========================================================================
__global__ __launch_bounds__(256) void match_partial_kernel(
    const float* __restrict__ W2, float* __restrict__ P)
{
    const int bz = blockIdx.z;
    const int b  = bz >> 1;
    const int s  = bz & 1;
    const int i0 = blockIdx.y * 64;
    const int j0 = blockIdx.x * 32;
    const int c0 = s * 128;

    const float* A  = g_h1 + (size_t)b * LL * HD;
    const float* Bm = g_h2 + (size_t)b * LL * HD;

    __shared__ __align__(16) float sAd[32][132];  // [kk][2i] duplicated
    __shared__ __align__(16) float sB [32][36];   // [kk][j] plain
    __shared__ __align__(16) float2 sw2d[128];    // (w,w)

    const int tid = threadIdx.x;
    const int ty = tid >> 4;       // rows 4ty..+3
    const int tx = tid & 15;       // cols 2tx, 2tx+1

    if (tid < 128) { float w = W2[c0 + tid]; sw2d[tid] = make_float2(w, w); }
    const u64p* swd = (const u64p*)sw2d;

    const int lm  = tid >> 3;        // 0..31
    const int lk4 = (tid & 7) * 4;   // 0..28

    u64p acc[4] = {};

    for (int kc = 0; kc < 128; kc += 32) {
        const int k0 = c0 + kc;
        float4 va0 = *(const float4*)&A [(size_t)(i0 + lm)      * HD + k0 + lk4];
        float4 va1 = *(const float4*)&A [(size_t)(i0 + 32 + lm) * HD + k0 + lk4];
        float4 vb  = *(const float4*)&Bm[(size_t)(j0 + lm)      * HD + k0 + lk4];
        __syncthreads();
        *(float2*)&sAd[lk4+0][2*lm]    = make_float2(va0.x, va0.x);
        *(float2*)&sAd[lk4+1][2*lm]    = make_float2(va0.y, va0.y);
        *(float2*)&sAd[lk4+2][2*lm]    = make_float2(va0.z, va0.z);
        *(float2*)&sAd[lk4+3][2*lm]    = make_float2(va0.w, va0.w);
        *(float2*)&sAd[lk4+0][64+2*lm] = make_float2(va1.x, va1.x);
        *(float2*)&sAd[lk4+1][64+2*lm] = make_float2(va1.y, va1.y);
        *(float2*)&sAd[lk4+2][64+2*lm] = make_float2(va1.z, va1.z);
        *(float2*)&sAd[lk4+3][64+2*lm] = make_float2(va1.w, va1.w);
        sB[lk4+0][lm] = vb.x; sB[lk4+1][lm] = vb.y; sB[lk4+2][lm] = vb.z; sB[lk4+3][lm] = vb.w;
        __syncthreads();

#pragma unroll
        for (int kk = 0; kk < 32; kk++) {
            const ulonglong2 ad0 = *(const ulonglong2*)&sAd[kk][ty*8];
            const ulonglong2 ad1 = *(const ulonglong2*)&sAd[kk][ty*8 + 4];
            const u64p       bp  = *(const u64p*)&sB[kk][tx*2];   // (b0,b1)
            const u64p       wd  = swd[kc + kk];                  // (w,w)
            acc[0] = f2_fma(f2_relu(f2_add(ad0.x, bp)), wd, acc[0]);
            acc[1] = f2_fma(f2_relu(f2_add(ad0.y, bp)), wd, acc[1]);
            acc[2] = f2_fma(f2_relu(f2_add(ad1.x, bp)), wd, acc[2]);
            acc[3] = f2_fma(f2_relu(f2_add(ad1.y, bp)), wd, acc[3]);
        }
    }

    float* Pd = P + ((size_t)(s*BB + b) * LL * LL);
#pragma unroll
    for (int u = 0; u < 4; u++) {
        float c0v, c1v;
        f2_unpack(acc[u], c0v, c1v);
        *(float2*)&Pd[(size_t)(i0 + ty*4 + u) * LL + j0 + tx*2] = make_float2(c0v, c1v);
    }
}

// =========================================================================
// K5: combine partials: out = sigmoid(P0 + P1 + b2)
// =========================================================================
__global__ __launch_bounds__(256) void combine_kernel(
    const float* __restrict__ P, const float* __restrict__ b2,
    float* __restrict__ out)
{
    const size_t n = (size_t)BB * LL * LL;
    const size_t idx = ((size_t)blockIdx.x * 256 + threadIdx.x) * 4;
    if (idx >= n) return;
    const float bias = b2[0];
    float4 p0 = *(const float4*)&P[idx];
    float4 p1 = *(const float4*)&P[n + idx];
    float4 o;
    o.x = 1.0f / (1.0f + __expf(-(p0.x + p1.x + bias)));
    o.y = 1.0f / (1.0f + __expf(-(p0.y + p1.y + bias)));
    o.z = 1.0f / (1.0f + __expf(-(p0.z + p1.z + bias)));
    o.w = 1.0f / (1.0f + __expf(-(p0.w + p1.w + bias)));
    *(float4*)&out[n + idx] = o;
}

// =========================================================================
extern "C" void kernel_launch(void* const* d_in, const int* in_sizes, int n_in,
                              void* d_out, int out_size)
{
    const float* e1  = (const float*)d_in[0];  // (B,L1,H)
    const float* e2  = (const float*)d_in[1];  // (B,L2,H)
    const float* ipw = (const float*)d_in[2];  // (3H,H)
    const float* ipb = (const float*)d_in[3];  // (3H,)
    const float* W1  = (const float*)d_in[4];  // (H,2H)
    const float* b1  = (const float*)d_in[5];  // (H,)
    const float* W2  = (const float*)d_in[6];  // (1,H)
    const float* b2  = (const float*)d_in[7];  // (1,)
    float* out = (float*)d_out;                // [attn (B,L1,L2)] ++ [match (B,L1,L2)]

    float* P;
    cudaGetSymbolAddress((void**)&P, g_logits);   // reuse logits buffer for partials

    proj_kernel   <<<dim3(HD/32, (BB*LL)/64, 4), 256>>>(e1, e2, ipw, ipb, W1, b1);
    logits_kernel <<<dim3(LL/64, LL/64, BB*NHEAD), 256>>>();
    softmax_mean_kernel<<<BB*LL, 256>>>(out);
    match_partial_kernel<<<dim3(LL/32, LL/64, BB*2), 256>>>(W2, P);
    combine_kernel<<<(BB*LL*LL/4 + 255)/256, 256>>>(P, b2, out);
}